// round 2
// baseline (speedup 1.0000x reference)
#include <cuda_runtime.h>
#include <cstdint>
#include <cstddef>

#define Hdim 64
#define Vdim 50257
#define Bdim 32
#define Ldim 4096

__device__ __align__(16) float g_htab[(size_t)Vdim * Hdim];
__device__ float g_nbeta[Vdim];
__device__ __align__(16) float g_M[(size_t)Bdim * Hdim * Hdim];
__device__ float g_rr[Bdim * Hdim];

// ---------------- Kernel 1: per-vocab encoder table ----------------
__global__ void __launch_bounds__(128) build_table_kernel(
    const float* __restrict__ embed, const float* __restrict__ w1,
    const float* __restrict__ b1, const float* __restrict__ w2,
    const float* __restrict__ b2, const float* __restrict__ lng,
    const float* __restrict__ lnb)
{
    __shared__ float es[16][Hdim + 1];
    __shared__ float hs[16][130];
    const int v0 = blockIdx.x * 16;
    const int tid = threadIdx.x;

    for (int idx = tid; idx < 16 * Hdim; idx += 128) {
        int r = idx >> 6, c = idx & 63;
        int v = v0 + r;
        es[r][c] = (v < Vdim) ? embed[(size_t)v * Hdim + c] : 0.f;
    }
    __syncthreads();

    const int r = tid >> 3;
    const int sub = tid & 7;

    { // hidden = relu(e @ w1 + b1), thread computes 16 of 128 units
        float acc[16];
        #pragma unroll
        for (int jj = 0; jj < 16; jj++) acc[jj] = b1[sub * 16 + jj];
        #pragma unroll 4
        for (int i = 0; i < Hdim; i++) {
            float ei = es[r][i];
            const float4* wp = (const float4*)(w1 + i * 128 + sub * 16);
            float4 wa = wp[0], wb = wp[1], wc = wp[2], wd = wp[3];
            acc[0]=fmaf(ei,wa.x,acc[0]);  acc[1]=fmaf(ei,wa.y,acc[1]);
            acc[2]=fmaf(ei,wa.z,acc[2]);  acc[3]=fmaf(ei,wa.w,acc[3]);
            acc[4]=fmaf(ei,wb.x,acc[4]);  acc[5]=fmaf(ei,wb.y,acc[5]);
            acc[6]=fmaf(ei,wb.z,acc[6]);  acc[7]=fmaf(ei,wb.w,acc[7]);
            acc[8]=fmaf(ei,wc.x,acc[8]);  acc[9]=fmaf(ei,wc.y,acc[9]);
            acc[10]=fmaf(ei,wc.z,acc[10]);acc[11]=fmaf(ei,wc.w,acc[11]);
            acc[12]=fmaf(ei,wd.x,acc[12]);acc[13]=fmaf(ei,wd.y,acc[13]);
            acc[14]=fmaf(ei,wd.z,acc[14]);acc[15]=fmaf(ei,wd.w,acc[15]);
        }
        #pragma unroll
        for (int jj = 0; jj < 16; jj++)
            hs[r][sub * 16 + jj] = fmaxf(acc[jj], 0.f);
    }
    __syncthreads();

    { // f = h @ w2 + b2 ; x = e + f ; LN ; write h_table, nbeta
        float f[8];
        #pragma unroll
        for (int ii = 0; ii < 8; ii++) f[ii] = b2[sub * 8 + ii];
        #pragma unroll 4
        for (int j = 0; j < 128; j++) {
            float hj = hs[r][j];
            const float4* wp = (const float4*)(w2 + j * Hdim + sub * 8);
            float4 wa = wp[0], wb = wp[1];
            f[0]=fmaf(hj,wa.x,f[0]); f[1]=fmaf(hj,wa.y,f[1]);
            f[2]=fmaf(hj,wa.z,f[2]); f[3]=fmaf(hj,wa.w,f[3]);
            f[4]=fmaf(hj,wb.x,f[4]); f[5]=fmaf(hj,wb.y,f[5]);
            f[6]=fmaf(hj,wb.z,f[6]); f[7]=fmaf(hj,wb.w,f[7]);
        }
        float x[8], s = 0.f, sq = 0.f;
        #pragma unroll
        for (int ii = 0; ii < 8; ii++) {
            x[ii] = es[r][sub * 8 + ii] + f[ii];
            s += x[ii];
            sq = fmaf(x[ii], x[ii], sq);
        }
        #pragma unroll
        for (int m = 1; m < 8; m <<= 1) {
            s  += __shfl_xor_sync(0xffffffffu, s,  m);
            sq += __shfl_xor_sync(0xffffffffu, sq, m);
        }
        float mu  = s * (1.f / 64.f);
        float var = sq * (1.f / 64.f) - mu * mu;
        float inv = rsqrtf(var + 1e-5f);
        float hh[8], kk = 0.f;
        #pragma unroll
        for (int ii = 0; ii < 8; ii++) {
            int col = sub * 8 + ii;
            hh[ii] = fmaf((x[ii] - mu) * inv, lng[col], lnb[col]);
            kk = fmaf(hh[ii], hh[ii], kk);
        }
        #pragma unroll
        for (int m = 1; m < 8; m <<= 1)
            kk += __shfl_xor_sync(0xffffffffu, kk, m);

        int v = v0 + r;
        if (v < Vdim) {
            float4* op = (float4*)(g_htab + (size_t)v * Hdim + sub * 8);
            op[0] = make_float4(hh[0], hh[1], hh[2], hh[3]);
            op[1] = make_float4(hh[4], hh[5], hh[6], hh[7]);
            if (sub == 0) g_nbeta[v] = -1.f / (kk + 1e-6f);
        }
    }
}

// ---------------- Kernel 2: delta-memory scan ----------------
#define RINGK 8
#define RINGID 16
#define DD1 6
#define DD2 13
#define KP 72

__global__ void __launch_bounds__(64, 1) scan_kernel(const int* __restrict__ seq)
{
    __shared__ __align__(16) float kring[2][RINGK][KP];
    __shared__ int idring[2][RINGID];

    const int b = blockIdx.x;
    const int g = blockIdx.y;
    const int tid = threadIdx.x;
    const int w = tid >> 5;
    const int lane = tid & 31;
    const int q = tid & 3;
    const int i = g * 16 + (tid >> 2);   // row of M this thread contributes to
    const int NS = Ldim - 1;
    const int* seqb = seq + (size_t)b * Ldim;

    if (lane < DD2) idring[w][lane] = seqb[lane];
    __syncwarp();
    for (int s = 0; s < DD1; s++) {
        int tok = idring[w][s];
        float2 kv = *(const float2*)(g_htab + (size_t)tok * Hdim + lane * 2);
        *(float2*)(&kring[w][s][lane * 2]) = kv;
        if (lane == 0) kring[w][s][Hdim] = g_nbeta[tok];
    }
    __syncwarp();

    float m[16];
    #pragma unroll
    for (int jj = 0; jj < 16; jj++) m[jj] = 0.f;

    float kx[16], kown, nb;
    {
        const float* sl = &kring[w][0][0];
        const float4* p = (const float4*)(sl + q * 16);
        float4 f0 = p[0], f1 = p[1], f2 = p[2], f3 = p[3];
        kx[0]=f0.x;kx[1]=f0.y;kx[2]=f0.z;kx[3]=f0.w;
        kx[4]=f1.x;kx[5]=f1.y;kx[6]=f1.z;kx[7]=f1.w;
        kx[8]=f2.x;kx[9]=f2.y;kx[10]=f2.z;kx[11]=f2.w;
        kx[12]=f3.x;kx[13]=f3.y;kx[14]=f3.z;kx[15]=f3.w;
        kown = sl[i];
        nb = sl[Hdim];
    }

    const unsigned kbase = (unsigned)__cvta_generic_to_shared(&kring[w][0][0]);
    const unsigned idbase = (unsigned)__cvta_generic_to_shared(&idring[w][0]);

    #pragma unroll 1
    for (int t = 0; t < NS; ++t) {
        asm volatile("cp.async.wait_group 4;" ::: "memory");
        __syncwarp();

        // compute step t
        float a0 = 0.f, a1 = 0.f, a2 = 0.f, a3 = 0.f;
        #pragma unroll
        for (int jj = 0; jj < 16; jj += 4) {
            a0 = fmaf(m[jj+0], kx[jj+0], a0);
            a1 = fmaf(m[jj+1], kx[jj+1], a1);
            a2 = fmaf(m[jj+2], kx[jj+2], a2);
            a3 = fmaf(m[jj+3], kx[jj+3], a3);
        }
        float vp = (a0 + a1) + (a2 + a3);
        vp += __shfl_xor_sync(0xffffffffu, vp, 1);
        vp += __shfl_xor_sync(0xffffffffu, vp, 2);
        float u = fmaf(nb, vp, kown);
        #pragma unroll
        for (int jj = 0; jj < 16; jj++) m[jj] = fmaf(u, kx[jj], m[jj]);

        // prefetch k for step t+DD1, token id for step t+DD2
        {
            int s1 = t + DD1;
            int tok1 = idring[w][s1 & (RINGID - 1)];
            unsigned dst = kbase + (unsigned)((s1 & (RINGK-1)) * (KP*4)) + (unsigned)(lane * 8);
            const float* src = g_htab + (size_t)tok1 * Hdim + lane * 2;
            asm volatile("cp.async.ca.shared.global [%0], [%1], 8;" :: "r"(dst), "l"(src));
            if (lane == 0) {
                unsigned dstb = kbase + (unsigned)((s1 & (RINGK-1)) * (KP*4)) + Hdim*4;
                asm volatile("cp.async.ca.shared.global [%0], [%1], 4;" :: "r"(dstb), "l"(g_nbeta + tok1));
                int t2 = t + DD2;
                int t2c = (t2 < Ldim) ? t2 : (Ldim - 1);
                unsigned dsti = idbase + (unsigned)((t2 & (RINGID-1)) * 4);
                asm volatile("cp.async.ca.shared.global [%0], [%1], 4;" :: "r"(dsti), "l"(seqb + t2c));
            }
        }
        asm volatile("cp.async.commit_group;" ::: "memory");

        // preload k for step t+1
        {
            const float* sl = &kring[w][(t + 1) & (RINGK - 1)][0];
            const float4* p = (const float4*)(sl + q * 16);
            float4 f0 = p[0], f1 = p[1], f2 = p[2], f3 = p[3];
            kx[0]=f0.x;kx[1]=f0.y;kx[2]=f0.z;kx[3]=f0.w;
            kx[4]=f1.x;kx[5]=f1.y;kx[6]=f1.z;kx[7]=f1.w;
            kx[8]=f2.x;kx[9]=f2.y;kx[10]=f2.z;kx[11]=f2.w;
            kx[12]=f3.x;kx[13]=f3.y;kx[14]=f3.z;kx[15]=f3.w;
            kown = sl[i];
            nb = sl[Hdim];
        }
    }

    float* Mp = g_M + (((size_t)b * Hdim + i) * Hdim) + q * 16;
    ((float4*)Mp)[0] = make_float4(m[0], m[1], m[2], m[3]);
    ((float4*)Mp)[1] = make_float4(m[4], m[5], m[6], m[7]);
    ((float4*)Mp)[2] = make_float4(m[8], m[9], m[10], m[11]);
    ((float4*)Mp)[3] = make_float4(m[12], m[13], m[14], m[15]);
}

// ---------------- Kernel 3: r = M q ; rr = r @ rp_w + rp_b ----------------
__global__ void __launch_bounds__(64) readout_kernel(
    const int* __restrict__ seq, const int* __restrict__ read_pos,
    const float* __restrict__ rp_w, const float* __restrict__ rp_b)
{
    __shared__ float qs[Hdim];
    __shared__ float rs[Hdim];
    const int b = blockIdx.x;
    const int tid = threadIdx.x;

    int rp = read_pos[0];
    if (rp < 0) rp += Ldim;
    int tok = seq[(size_t)b * Ldim + rp];
    qs[tid] = g_htab[(size_t)tok * Hdim + tid];
    __syncthreads();

    const float* Mi = g_M + ((size_t)b * Hdim + tid) * Hdim;
    float r = 0.f;
    #pragma unroll 8
    for (int j = 0; j < Hdim; j++) r = fmaf(Mi[j], qs[j], r);
    rs[tid] = r;
    __syncthreads();

    float acc = rp_b[tid];
    #pragma unroll 8
    for (int k = 0; k < Hdim; k++) acc = fmaf(rs[k], rp_w[k * Hdim + tid], acc);
    g_rr[b * Hdim + tid] = acc;
}

// ---------------- Kernel 4: logits ----------------
__global__ void __launch_bounds__(256) logits_kernel(
    const float* __restrict__ out_w, const float* __restrict__ out_b,
    float* __restrict__ out)
{
    __shared__ float rrs[Bdim * Hdim];
    const int tid = threadIdx.x;
    for (int idx = tid; idx < Bdim * Hdim; idx += 256) rrs[idx] = g_rr[idx];
    __syncthreads();

    const int v = blockIdx.x * 256 + tid;
    if (v >= Vdim) return;

    float acc[Bdim];
    #pragma unroll
    for (int bb = 0; bb < Bdim; bb++) acc[bb] = 0.f;
    #pragma unroll 4
    for (int i = 0; i < Hdim; i++) {
        float wv = out_w[(size_t)i * Vdim + v];
        #pragma unroll
        for (int bb = 0; bb < Bdim; bb++)
            acc[bb] = fmaf(rrs[bb * Hdim + i], wv, acc[bb]);
    }
    float ob = out_b[v];
    #pragma unroll
    for (int bb = 0; bb < Bdim; bb++)
        out[(size_t)bb * Vdim + v] = acc[bb] + ob;
}

// ----------------------------------------------------------------
extern "C" void kernel_launch(void* const* d_in, const int* in_sizes, int n_in,
                              void* d_out, int out_size)
{
    const int*   seq      = (const int*)d_in[0];
    const int*   read_pos = (const int*)d_in[1];
    const float* embed    = (const float*)d_in[2];
    const float* w1       = (const float*)d_in[3];
    const float* b1       = (const float*)d_in[4];
    const float* w2       = (const float*)d_in[5];
    const float* b2       = (const float*)d_in[6];
    const float* ln_g     = (const float*)d_in[7];
    const float* ln_b     = (const float*)d_in[8];
    const float* rp_w     = (const float*)d_in[9];
    const float* rp_b     = (const float*)d_in[10];
    const float* out_w    = (const float*)d_in[11];
    const float* out_b    = (const float*)d_in[12];
    float* out = (float*)d_out;

    build_table_kernel<<<(Vdim + 15) / 16, 128>>>(embed, w1, b1, w2, b2, ln_g, ln_b);
    scan_kernel<<<dim3(Bdim, 4), 64>>>(seq);
    readout_kernel<<<Bdim, Hdim>>>(seq, read_pos, rp_w, rp_b);
    logits_kernel<<<(Vdim + 255) / 256, 256>>>(out_w, out_b, out);
}

// round 3
// speedup vs baseline: 1.0971x; 1.0971x over previous
#include <cuda_runtime.h>
#include <cstdint>
#include <cstddef>

#define Hdim 64
#define Vdim 50257
#define Bdim 32
#define Ldim 4096
#define NSTEP (Ldim - 1)      // 4095 keys
#define CNKS 64               // 64 chunks of 64 (last has 63 valid)

__device__ __align__(16) float g_htab[(size_t)Vdim * Hdim];
__device__ float g_nbeta[Vdim];
__device__ __align__(16) float g_M[(size_t)Bdim * Hdim * Hdim];
__device__ float g_rr[Bdim * Hdim];
__device__ __align__(16) float g_G[(size_t)Bdim * CNKS * 64 * 64];   // 33.5 MB

// ---------------- Kernel 1: per-vocab encoder table ----------------
__global__ void __launch_bounds__(128) build_table_kernel(
    const float* __restrict__ embed, const float* __restrict__ w1,
    const float* __restrict__ b1, const float* __restrict__ w2,
    const float* __restrict__ b2, const float* __restrict__ lng,
    const float* __restrict__ lnb)
{
    __shared__ float es[16][Hdim + 1];
    __shared__ float hs[16][130];
    const int v0 = blockIdx.x * 16;
    const int tid = threadIdx.x;

    for (int idx = tid; idx < 16 * Hdim; idx += 128) {
        int r = idx >> 6, c = idx & 63;
        int v = v0 + r;
        es[r][c] = (v < Vdim) ? embed[(size_t)v * Hdim + c] : 0.f;
    }
    __syncthreads();

    const int r = tid >> 3;
    const int sub = tid & 7;

    {
        float acc[16];
        #pragma unroll
        for (int jj = 0; jj < 16; jj++) acc[jj] = b1[sub * 16 + jj];
        #pragma unroll 4
        for (int i = 0; i < Hdim; i++) {
            float ei = es[r][i];
            const float4* wp = (const float4*)(w1 + i * 128 + sub * 16);
            float4 wa = wp[0], wb = wp[1], wc = wp[2], wd = wp[3];
            acc[0]=fmaf(ei,wa.x,acc[0]);  acc[1]=fmaf(ei,wa.y,acc[1]);
            acc[2]=fmaf(ei,wa.z,acc[2]);  acc[3]=fmaf(ei,wa.w,acc[3]);
            acc[4]=fmaf(ei,wb.x,acc[4]);  acc[5]=fmaf(ei,wb.y,acc[5]);
            acc[6]=fmaf(ei,wb.z,acc[6]);  acc[7]=fmaf(ei,wb.w,acc[7]);
            acc[8]=fmaf(ei,wc.x,acc[8]);  acc[9]=fmaf(ei,wc.y,acc[9]);
            acc[10]=fmaf(ei,wc.z,acc[10]);acc[11]=fmaf(ei,wc.w,acc[11]);
            acc[12]=fmaf(ei,wd.x,acc[12]);acc[13]=fmaf(ei,wd.y,acc[13]);
            acc[14]=fmaf(ei,wd.z,acc[14]);acc[15]=fmaf(ei,wd.w,acc[15]);
        }
        #pragma unroll
        for (int jj = 0; jj < 16; jj++)
            hs[r][sub * 16 + jj] = fmaxf(acc[jj], 0.f);
    }
    __syncthreads();

    {
        float f[8];
        #pragma unroll
        for (int ii = 0; ii < 8; ii++) f[ii] = b2[sub * 8 + ii];
        #pragma unroll 4
        for (int j = 0; j < 128; j++) {
            float hj = hs[r][j];
            const float4* wp = (const float4*)(w2 + j * Hdim + sub * 8);
            float4 wa = wp[0], wb = wp[1];
            f[0]=fmaf(hj,wa.x,f[0]); f[1]=fmaf(hj,wa.y,f[1]);
            f[2]=fmaf(hj,wa.z,f[2]); f[3]=fmaf(hj,wa.w,f[3]);
            f[4]=fmaf(hj,wb.x,f[4]); f[5]=fmaf(hj,wb.y,f[5]);
            f[6]=fmaf(hj,wb.z,f[6]); f[7]=fmaf(hj,wb.w,f[7]);
        }
        float x[8], s = 0.f, sq = 0.f;
        #pragma unroll
        for (int ii = 0; ii < 8; ii++) {
            x[ii] = es[r][sub * 8 + ii] + f[ii];
            s += x[ii];
            sq = fmaf(x[ii], x[ii], sq);
        }
        #pragma unroll
        for (int m = 1; m < 8; m <<= 1) {
            s  += __shfl_xor_sync(0xffffffffu, s,  m);
            sq += __shfl_xor_sync(0xffffffffu, sq, m);
        }
        float mu  = s * (1.f / 64.f);
        float var = sq * (1.f / 64.f) - mu * mu;
        float inv = rsqrtf(var + 1e-5f);
        float hh[8], kk = 0.f;
        #pragma unroll
        for (int ii = 0; ii < 8; ii++) {
            int col = sub * 8 + ii;
            hh[ii] = fmaf((x[ii] - mu) * inv, lng[col], lnb[col]);
            kk = fmaf(hh[ii], hh[ii], kk);
        }
        #pragma unroll
        for (int m = 1; m < 8; m <<= 1)
            kk += __shfl_xor_sync(0xffffffffu, kk, m);

        int v = v0 + r;
        if (v < Vdim) {
            float4* op = (float4*)(g_htab + (size_t)v * Hdim + sub * 8);
            op[0] = make_float4(hh[0], hh[1], hh[2], hh[3]);
            op[1] = make_float4(hh[4], hh[5], hh[6], hh[7]);
            if (sub == 0) g_nbeta[v] = -1.f / (kk + 1e-6f);
        }
    }
}

// ---------------- Kernel 2: per-chunk Gram matrices ----------------
// G[b][c][s][t] = k_s . k_t  for s < t (else 0).  Fully parallel.
__global__ void __launch_bounds__(128) gram_kernel(const int* __restrict__ seq)
{
    __shared__ float Kt[64][68];   // [dim j][step t]
    const int b = blockIdx.x;
    const int c = blockIdx.y;
    const int z = threadIdx.x;
    const int r = z >> 1, ih = z & 1;

    int gstep = c * 64 + r;
    if (gstep < NSTEP) {
        int tok = seq[(size_t)b * Ldim + gstep];
        const float4* src = (const float4*)(g_htab + (size_t)tok * Hdim + ih * 32);
        #pragma unroll
        for (int m = 0; m < 8; m++) {
            float4 v = src[m];
            int j = ih * 32 + m * 4;
            Kt[j][r] = v.x; Kt[j+1][r] = v.y; Kt[j+2][r] = v.z; Kt[j+3][r] = v.w;
        }
    } else {
        #pragma unroll
        for (int m = 0; m < 8; m++) {
            int j = ih * 32 + m * 4;
            Kt[j][r] = 0.f; Kt[j+1][r] = 0.f; Kt[j+2][r] = 0.f; Kt[j+3][r] = 0.f;
        }
    }
    __syncthreads();

    const int sb = z >> 3;   // s-group: 4 s values
    const int tb = z & 7;    // t-group: 8 t values
    float acc[4][8];
    #pragma unroll
    for (int a = 0; a < 4; a++)
        #pragma unroll
        for (int m = 0; m < 8; m++) acc[a][m] = 0.f;

    #pragma unroll 4
    for (int j = 0; j < 64; j++) {
        float4 ks = *(const float4*)&Kt[j][4 * sb];
        float4 ta = *(const float4*)&Kt[j][8 * tb];
        float4 tbv = *(const float4*)&Kt[j][8 * tb + 4];
        float tv[8] = {ta.x, ta.y, ta.z, ta.w, tbv.x, tbv.y, tbv.z, tbv.w};
        float sv[4] = {ks.x, ks.y, ks.z, ks.w};
        #pragma unroll
        for (int a = 0; a < 4; a++)
            #pragma unroll
            for (int m = 0; m < 8; m++)
                acc[a][m] = fmaf(sv[a], tv[m], acc[a][m]);
    }

    float* Gp = g_G + (((size_t)b * CNKS + c) << 12);
    #pragma unroll
    for (int a = 0; a < 4; a++) {
        int s = 4 * sb + a;
        float ov[8];
        #pragma unroll
        for (int m = 0; m < 8; m++) {
            int t = 8 * tb + m;
            ov[m] = (s < t) ? acc[a][m] : 0.f;
        }
        *(float4*)&Gp[s * 64 + 8 * tb]     = make_float4(ov[0], ov[1], ov[2], ov[3]);
        *(float4*)&Gp[s * 64 + 8 * tb + 4] = make_float4(ov[4], ov[5], ov[6], ov[7]);
    }
}

// ---------------- Kernel 3: chunked delta-memory scan ----------------
struct ScanSmem {
    float Ksh[2][64][68];   // [buf][step s][dim j]
    float Gsh[2][64][64];   // [buf][s][t]
    float Mt[64][20];       // [dim j][row il]  (M transposed)
    float Dsh[64][16];      // [t][il]
    float Ush[64][16];      // [s][il]
    float nbsh[2][64];
};
#define SCAN_SMEM_BYTES sizeof(ScanSmem)

__device__ __forceinline__ void cpasync16(unsigned dst, const void* src) {
    asm volatile("cp.async.ca.shared.global [%0], [%1], 16;" :: "r"(dst), "l"(src));
}
__device__ __forceinline__ void cpasync4(unsigned dst, const void* src) {
    asm volatile("cp.async.ca.shared.global [%0], [%1], 4;" :: "r"(dst), "l"(src));
}

__global__ void __launch_bounds__(128, 1) scan2_kernel(const int* __restrict__ seq)
{
    extern __shared__ __align__(16) char smem_raw[];
    ScanSmem* S = (ScanSmem*)smem_raw;

    const int b = blockIdx.x;
    const int i0 = blockIdx.y * 16;        // row group base
    const int z = threadIdx.x;
    const int r = z >> 1, ih = z & 1;      // staging / d0 / M-update mapping
    const int il = z >> 3, tq = z & 7;     // solve mapping
    const int lane = z & 31;
    const int* seqb = seq + (size_t)b * Ldim;

    // zero M
    for (int idx = z; idx < 64 * 20; idx += 128) ((float*)S->Mt)[idx] = 0.f;

    // token pipeline
    int tokA = 0, tokB = 0; bool vA = false, vB = false;
    {
        int g0 = r;                                   // chunk 0
        vA = g0 < NSTEP; tokA = vA ? seqb[g0] : 0;
        int g1 = 64 + r;                              // chunk 1
        vB = g1 < NSTEP; tokB = vB ? seqb[g1] : 0;
    }

    // ---- fill buffer 0 (chunk 0) ----
    {
        if (vA) {
            const float* src = g_htab + (size_t)tokA * Hdim + ih * 32;
            unsigned dst = (unsigned)__cvta_generic_to_shared(&S->Ksh[0][r][ih * 32]);
            #pragma unroll
            for (int m = 0; m < 8; m++) cpasync16(dst + m * 16, src + m * 4);
            if (ih == 0)
                cpasync4((unsigned)__cvta_generic_to_shared(&S->nbsh[0][r]), g_nbeta + tokA);
        } else {
            float4 zz = make_float4(0.f, 0.f, 0.f, 0.f);
            #pragma unroll
            for (int m = 0; m < 8; m++) *(float4*)&S->Ksh[0][r][ih * 32 + 4 * m] = zz;
            if (ih == 0) S->nbsh[0][r] = 0.f;
        }
        const float* gsrc = g_G + (((size_t)b * CNKS + 0) << 12);
        unsigned gdst = (unsigned)__cvta_generic_to_shared(&S->Gsh[0][0][0]);
        #pragma unroll
        for (int m = 0; m < 8; m++) {
            int idx = z + 128 * m;
            cpasync16(gdst + idx * 16, gsrc + idx * 4);
        }
        asm volatile("cp.async.commit_group;" ::: "memory");
        asm volatile("cp.async.wait_group 0;" ::: "memory");
        __syncthreads();
    }

    #pragma unroll 1
    for (int c = 0; c < CNKS; ++c) {
        const int cur = c & 1;

        // ---- prefetch chunk c+1 into other buffer ----
        if (c + 1 < CNKS) {
            const int nb_ = cur ^ 1;
            if (vB) {
                const float* src = g_htab + (size_t)tokB * Hdim + ih * 32;
                unsigned dst = (unsigned)__cvta_generic_to_shared(&S->Ksh[nb_][r][ih * 32]);
                #pragma unroll
                for (int m = 0; m < 8; m++) cpasync16(dst + m * 16, src + m * 4);
                if (ih == 0)
                    cpasync4((unsigned)__cvta_generic_to_shared(&S->nbsh[nb_][r]), g_nbeta + tokB);
            } else {
                float4 zz = make_float4(0.f, 0.f, 0.f, 0.f);
                #pragma unroll
                for (int m = 0; m < 8; m++) *(float4*)&S->Ksh[nb_][r][ih * 32 + 4 * m] = zz;
                if (ih == 0) S->nbsh[nb_][r] = 0.f;
            }
            const float* gsrc = g_G + (((size_t)b * CNKS + (c + 1)) << 12);
            unsigned gdst = (unsigned)__cvta_generic_to_shared(&S->Gsh[nb_][0][0]);
            #pragma unroll
            for (int m = 0; m < 8; m++) {
                int idx = z + 128 * m;
                cpasync16(gdst + idx * 16, gsrc + idx * 4);
            }
        }
        asm volatile("cp.async.commit_group;" ::: "memory");

        // advance token pipeline (chunk c+2) — latency hidden behind phases
        {
            int c2 = c + 2;
            int g2 = c2 * 64 + r;
            vB = (c2 < CNKS) && (g2 < NSTEP);
            tokB = vB ? seqb[vB ? g2 : 0] : 0;
        }

        // ---- phase 1: D[t][i] = sum_j M[i][j] * K[t][j] ----
        {
            const int t = r;
            float acc[8];
            #pragma unroll
            for (int m = 0; m < 8; m++) acc[m] = 0.f;
            const float* Kr = &S->Ksh[cur][t][0];
            #pragma unroll 4
            for (int j = 0; j < 64; j++) {
                float kv = Kr[j];
                float4 m0 = *(const float4*)&S->Mt[j][8 * ih];
                float4 m1 = *(const float4*)&S->Mt[j][8 * ih + 4];
                acc[0] = fmaf(kv, m0.x, acc[0]);
                acc[1] = fmaf(kv, m0.y, acc[1]);
                acc[2] = fmaf(kv, m0.z, acc[2]);
                acc[3] = fmaf(kv, m0.w, acc[3]);
                acc[4] = fmaf(kv, m1.x, acc[4]);
                acc[5] = fmaf(kv, m1.y, acc[5]);
                acc[6] = fmaf(kv, m1.z, acc[6]);
                acc[7] = fmaf(kv, m1.w, acc[7]);
            }
            *(float4*)&S->Dsh[t][8 * ih]     = make_float4(acc[0], acc[1], acc[2], acc[3]);
            *(float4*)&S->Dsh[t][8 * ih + 4] = make_float4(acc[4], acc[5], acc[6], acc[7]);
        }
        __syncthreads();

        // ---- phase 2: triangular solve for U ----
        {
            float vp[8];
            #pragma unroll
            for (int m = 0; m < 8; m++) vp[m] = S->Dsh[8 * tq + m][il];
            const int gi = i0 + il;
            const float* Ks = &S->Ksh[cur][0][0];
            const float* nbp = &S->nbsh[cur][0];
            const float* Gp = &S->Gsh[cur][0][0];
            const int srcbase = lane & 24;

            #pragma unroll 1
            for (int blk = 0; blk < 8; ++blk) {
                #pragma unroll
                for (int m8 = 0; m8 < 8; ++m8) {
                    const int s = blk * 8 + m8;
                    float kv  = Ks[s * 68 + gi];
                    float nbv = nbp[s];
                    float cu  = fmaf(nbv, vp[m8], kv);   // valid only on owner (tq==blk)
                    float ub  = __shfl_sync(0xffffffffu, cu, srcbase | blk);
                    if (tq == 0) S->Ush[s][il] = ub;
                    float4 ga = *(const float4*)&Gp[s * 64 + 8 * tq];
                    float4 gb = *(const float4*)&Gp[s * 64 + 8 * tq + 4];
                    vp[0] = fmaf(ub, ga.x, vp[0]);
                    vp[1] = fmaf(ub, ga.y, vp[1]);
                    vp[2] = fmaf(ub, ga.z, vp[2]);
                    vp[3] = fmaf(ub, ga.w, vp[3]);
                    vp[4] = fmaf(ub, gb.x, vp[4]);
                    vp[5] = fmaf(ub, gb.y, vp[5]);
                    vp[6] = fmaf(ub, gb.z, vp[6]);
                    vp[7] = fmaf(ub, gb.w, vp[7]);
                }
            }
        }
        __syncthreads();

        // ---- phase 3: M[i][j] += sum_s u[s][i] * K[s][j] ----
        {
            const int j = r;
            float4 a = *(const float4*)&S->Mt[j][8 * ih];
            float4 bq = *(const float4*)&S->Mt[j][8 * ih + 4];
            float mr[8] = {a.x, a.y, a.z, a.w, bq.x, bq.y, bq.z, bq.w};
            const float* Ks = &S->Ksh[cur][0][0];
            #pragma unroll 4
            for (int s = 0; s < 64; s++) {
                float kv = Ks[s * 68 + j];
                float4 u0 = *(const float4*)&S->Ush[s][8 * ih];
                float4 u1 = *(const float4*)&S->Ush[s][8 * ih + 4];
                mr[0] = fmaf(u0.x, kv, mr[0]);
                mr[1] = fmaf(u0.y, kv, mr[1]);
                mr[2] = fmaf(u0.z, kv, mr[2]);
                mr[3] = fmaf(u0.w, kv, mr[3]);
                mr[4] = fmaf(u1.x, kv, mr[4]);
                mr[5] = fmaf(u1.y, kv, mr[5]);
                mr[6] = fmaf(u1.z, kv, mr[6]);
                mr[7] = fmaf(u1.w, kv, mr[7]);
            }
            *(float4*)&S->Mt[j][8 * ih]     = make_float4(mr[0], mr[1], mr[2], mr[3]);
            *(float4*)&S->Mt[j][8 * ih + 4] = make_float4(mr[4], mr[5], mr[6], mr[7]);
        }
        asm volatile("cp.async.wait_group 0;" ::: "memory");
        __syncthreads();
    }

    // ---- write back M (row-major g_M[b][i][j]) ----
    for (int idx = z; idx < 16 * 64; idx += 128) {
        int ii = idx & 15, j = idx >> 4;
        g_M[((size_t)b * Hdim + i0 + ii) * Hdim + j] = S->Mt[j][ii];
    }
}

// ---------------- Kernel 4: r = M q ; rr = r @ rp_w + rp_b ----------------
__global__ void __launch_bounds__(64) readout_kernel(
    const int* __restrict__ seq, const int* __restrict__ read_pos,
    const float* __restrict__ rp_w, const float* __restrict__ rp_b)
{
    __shared__ float qs[Hdim];
    __shared__ float rs[Hdim];
    const int b = blockIdx.x;
    const int tid = threadIdx.x;

    int rp = read_pos[0];
    if (rp < 0) rp += Ldim;
    int tok = seq[(size_t)b * Ldim + rp];
    qs[tid] = g_htab[(size_t)tok * Hdim + tid];
    __syncthreads();

    const float* Mi = g_M + ((size_t)b * Hdim + tid) * Hdim;
    float r = 0.f;
    #pragma unroll 8
    for (int j = 0; j < Hdim; j++) r = fmaf(Mi[j], qs[j], r);
    rs[tid] = r;
    __syncthreads();

    float acc = rp_b[tid];
    #pragma unroll 8
    for (int k = 0; k < Hdim; k++) acc = fmaf(rs[k], rp_w[k * Hdim + tid], acc);
    g_rr[b * Hdim + tid] = acc;
}

// ---------------- Kernel 5: logits ----------------
__global__ void __launch_bounds__(128) logits_kernel(
    const float* __restrict__ out_w, const float* __restrict__ out_b,
    float* __restrict__ out)
{
    __shared__ float rrs[8 * Hdim];
    const int tid = threadIdx.x;
    const int bg = blockIdx.y;      // 8 batches per y-slice
    for (int idx = tid; idx < 8 * Hdim; idx += 128)
        rrs[idx] = g_rr[bg * 8 * Hdim + idx];
    __syncthreads();

    const int v = blockIdx.x * 128 + tid;
    if (v >= Vdim) return;

    float acc[8];
    #pragma unroll
    for (int bb = 0; bb < 8; bb++) acc[bb] = 0.f;
    #pragma unroll 8
    for (int i = 0; i < Hdim; i++) {
        float wv = out_w[(size_t)i * Vdim + v];
        #pragma unroll
        for (int bb = 0; bb < 8; bb++)
            acc[bb] = fmaf(rrs[bb * Hdim + i], wv, acc[bb]);
    }
    float ob = out_b[v];
    #pragma unroll
    for (int bb = 0; bb < 8; bb++)
        out[(size_t)(bg * 8 + bb) * Vdim + v] = acc[bb] + ob;
}

// ----------------------------------------------------------------
extern "C" void kernel_launch(void* const* d_in, const int* in_sizes, int n_in,
                              void* d_out, int out_size)
{
    const int*   seq      = (const int*)d_in[0];
    const int*   read_pos = (const int*)d_in[1];
    const float* embed    = (const float*)d_in[2];
    const float* w1       = (const float*)d_in[3];
    const float* b1       = (const float*)d_in[4];
    const float* w2       = (const float*)d_in[5];
    const float* b2       = (const float*)d_in[6];
    const float* ln_g     = (const float*)d_in[7];
    const float* ln_b     = (const float*)d_in[8];
    const float* rp_w     = (const float*)d_in[9];
    const float* rp_b     = (const float*)d_in[10];
    const float* out_w    = (const float*)d_in[11];
    const float* out_b    = (const float*)d_in[12];
    float* out = (float*)d_out;

    static bool attr_done = false;
    if (!attr_done) {
        cudaFuncSetAttribute(scan2_kernel,
                             cudaFuncAttributeMaxDynamicSharedMemorySize,
                             (int)SCAN_SMEM_BYTES);
        attr_done = true;
    }

    build_table_kernel<<<(Vdim + 15) / 16, 128>>>(embed, w1, b1, w2, b2, ln_g, ln_b);
    gram_kernel<<<dim3(Bdim, CNKS), 128>>>(seq);
    scan2_kernel<<<dim3(Bdim, 4), 128, SCAN_SMEM_BYTES>>>(seq);
    readout_kernel<<<Bdim, Hdim>>>(seq, read_pos, rp_w, rp_b);
    logits_kernel<<<dim3((Vdim + 127) / 128, 4), 128>>>(out_w, out_b, out);
}

// round 4
// speedup vs baseline: 1.1160x; 1.0172x over previous
#include <cuda_runtime.h>
#include <cstdint>
#include <cstddef>

#define Hdim 64
#define Vdim 50257
#define Bdim 32
#define Ldim 4096
#define NSTEP (Ldim - 1)
#define CNKS 64

using u64 = unsigned long long;

__device__ __forceinline__ u64 pk2(float lo, float hi) {
    u64 r; asm("mov.b64 %0,{%1,%2};" : "=l"(r) : "f"(lo), "f"(hi)); return r;
}
__device__ __forceinline__ void up2(u64 v, float& lo, float& hi) {
    asm("mov.b64 {%0,%1},%2;" : "=f"(lo), "=f"(hi) : "l"(v));
}
__device__ __forceinline__ u64 ff2(u64 a, u64 b, u64 c) {
    u64 d; asm("fma.rn.f32x2 %0,%1,%2,%3;" : "=l"(d) : "l"(a), "l"(b), "l"(c)); return d;
}

__device__ __align__(16) float g_htab[(size_t)Vdim * Hdim];
__device__ float g_nbeta[Vdim];
__device__ __align__(16) float g_M[(size_t)Bdim * Hdim * Hdim];
__device__ float g_rr[Bdim * Hdim];
__device__ __align__(16) float g_G[(size_t)Bdim * CNKS * 64 * 64];

__device__ __forceinline__ void cpasync16(unsigned dst, const void* src) {
    asm volatile("cp.async.ca.shared.global [%0], [%1], 16;" :: "r"(dst), "l"(src));
}
__device__ __forceinline__ void cpasync4(unsigned dst, const void* src) {
    asm volatile("cp.async.ca.shared.global [%0], [%1], 4;" :: "r"(dst), "l"(src));
}

// ---------------- Kernel 1: per-vocab encoder table (smem weights + f32x2) ----------------
struct TabSmem {
    float w1s[64 * 128];
    float w2s[128 * 64];
    float es[16][65];
    float hs[16][132];
};
#define TAB_SMEM_BYTES sizeof(TabSmem)

__global__ void __launch_bounds__(128) build_table_kernel(
    const float* __restrict__ embed, const float* __restrict__ w1,
    const float* __restrict__ b1, const float* __restrict__ w2,
    const float* __restrict__ b2, const float* __restrict__ lng,
    const float* __restrict__ lnb)
{
    extern __shared__ __align__(16) char tsm_raw[];
    TabSmem* S = (TabSmem*)tsm_raw;
    const int v0 = blockIdx.x * 16;
    const int tid = threadIdx.x;

    // stage weights (coalesced float4)
    {
        const float4* w1g = (const float4*)w1;
        float4* w1d = (float4*)S->w1s;
        const float4* w2g = (const float4*)w2;
        float4* w2d = (float4*)S->w2s;
        #pragma unroll
        for (int m = 0; m < 16; m++) {
            int idx = tid + 128 * m;
            w1d[idx] = w1g[idx];
            w2d[idx] = w2g[idx];
        }
    }
    for (int idx = tid; idx < 16 * Hdim; idx += 128) {
        int r = idx >> 6, c = idx & 63;
        int v = v0 + r;
        S->es[r][c] = (v < Vdim) ? embed[(size_t)v * Hdim + c] : 0.f;
    }
    __syncthreads();

    const int r = tid >> 3;
    const int sub = tid & 7;

    { // hidden = relu(e @ w1 + b1): 16 outputs per thread, packed
        u64 acc[8];
        #pragma unroll
        for (int m = 0; m < 8; m++)
            acc[m] = pk2(b1[sub * 16 + 2 * m], b1[sub * 16 + 2 * m + 1]);
        #pragma unroll 4
        for (int i = 0; i < Hdim; i++) {
            float ei = S->es[r][i];
            u64 eib = pk2(ei, ei);
            const u64* wp = (const u64*)&S->w1s[i * 128 + sub * 16];
            #pragma unroll
            for (int m = 0; m < 8; m++) acc[m] = ff2(eib, wp[m], acc[m]);
        }
        #pragma unroll
        for (int m = 0; m < 8; m++) {
            float a, bq; up2(acc[m], a, bq);
            S->hs[r][sub * 16 + 2 * m]     = fmaxf(a, 0.f);
            S->hs[r][sub * 16 + 2 * m + 1] = fmaxf(bq, 0.f);
        }
    }
    __syncthreads();

    { // f = h @ w2 + b2 ; x = e + f ; LN
        u64 fp[4];
        #pragma unroll
        for (int m = 0; m < 4; m++)
            fp[m] = pk2(b2[sub * 8 + 2 * m], b2[sub * 8 + 2 * m + 1]);
        #pragma unroll 4
        for (int j = 0; j < 128; j++) {
            float hj = S->hs[r][j];
            u64 hb = pk2(hj, hj);
            const u64* wp = (const u64*)&S->w2s[j * 64 + sub * 8];
            #pragma unroll
            for (int m = 0; m < 4; m++) fp[m] = ff2(hb, wp[m], fp[m]);
        }
        float f[8];
        #pragma unroll
        for (int m = 0; m < 4; m++) up2(fp[m], f[2 * m], f[2 * m + 1]);

        float x[8], s = 0.f, sq = 0.f;
        #pragma unroll
        for (int ii = 0; ii < 8; ii++) {
            x[ii] = S->es[r][sub * 8 + ii] + f[ii];
            s += x[ii];
            sq = fmaf(x[ii], x[ii], sq);
        }
        #pragma unroll
        for (int m = 1; m < 8; m <<= 1) {
            s  += __shfl_xor_sync(0xffffffffu, s,  m);
            sq += __shfl_xor_sync(0xffffffffu, sq, m);
        }
        float mu  = s * (1.f / 64.f);
        float var = sq * (1.f / 64.f) - mu * mu;
        float inv = rsqrtf(var + 1e-5f);
        float hh[8], kk = 0.f;
        #pragma unroll
        for (int ii = 0; ii < 8; ii++) {
            int col = sub * 8 + ii;
            hh[ii] = fmaf((x[ii] - mu) * inv, lng[col], lnb[col]);
            kk = fmaf(hh[ii], hh[ii], kk);
        }
        #pragma unroll
        for (int m = 1; m < 8; m <<= 1)
            kk += __shfl_xor_sync(0xffffffffu, kk, m);

        int v = v0 + r;
        if (v < Vdim) {
            float4* op = (float4*)(g_htab + (size_t)v * Hdim + sub * 8);
            op[0] = make_float4(hh[0], hh[1], hh[2], hh[3]);
            op[1] = make_float4(hh[4], hh[5], hh[6], hh[7]);
            if (sub == 0) g_nbeta[v] = -1.f / (kk + 1e-6f);
        }
    }
}

// ---------------- Kernel 2: per-chunk Gram matrices (f32x2) ----------------
__global__ void __launch_bounds__(128) gram_kernel(const int* __restrict__ seq)
{
    __shared__ float Kt[64][68];
    const int b = blockIdx.x;
    const int c = blockIdx.y;
    const int z = threadIdx.x;
    const int r = z >> 1, ih = z & 1;

    int gstep = c * 64 + r;
    if (gstep < NSTEP) {
        int tok = seq[(size_t)b * Ldim + gstep];
        const float4* src = (const float4*)(g_htab + (size_t)tok * Hdim + ih * 32);
        #pragma unroll
        for (int m = 0; m < 8; m++) {
            float4 v = src[m];
            int j = ih * 32 + m * 4;
            Kt[j][r] = v.x; Kt[j+1][r] = v.y; Kt[j+2][r] = v.z; Kt[j+3][r] = v.w;
        }
    } else {
        #pragma unroll
        for (int m = 0; m < 8; m++) {
            int j = ih * 32 + m * 4;
            Kt[j][r] = 0.f; Kt[j+1][r] = 0.f; Kt[j+2][r] = 0.f; Kt[j+3][r] = 0.f;
        }
    }
    __syncthreads();

    const int sb = z >> 3;
    const int tb = z & 7;
    u64 acc[4][4];
    #pragma unroll
    for (int a = 0; a < 4; a++)
        #pragma unroll
        for (int m = 0; m < 4; m++) acc[a][m] = 0ULL;

    #pragma unroll 4
    for (int j = 0; j < 64; j++) {
        float4 ks = *(const float4*)&Kt[j][4 * sb];
        const u64* tp = (const u64*)&Kt[j][8 * tb];
        u64 t0 = tp[0], t1 = tp[1], t2 = tp[2], t3 = tp[3];
        u64 sv[4] = {pk2(ks.x, ks.x), pk2(ks.y, ks.y), pk2(ks.z, ks.z), pk2(ks.w, ks.w)};
        #pragma unroll
        for (int a = 0; a < 4; a++) {
            acc[a][0] = ff2(sv[a], t0, acc[a][0]);
            acc[a][1] = ff2(sv[a], t1, acc[a][1]);
            acc[a][2] = ff2(sv[a], t2, acc[a][2]);
            acc[a][3] = ff2(sv[a], t3, acc[a][3]);
        }
    }

    float* Gp = g_G + (((size_t)b * CNKS + c) << 12);
    #pragma unroll
    for (int a = 0; a < 4; a++) {
        int s = 4 * sb + a;
        float ov[8];
        #pragma unroll
        for (int m = 0; m < 4; m++) up2(acc[a][m], ov[2 * m], ov[2 * m + 1]);
        #pragma unroll
        for (int m = 0; m < 8; m++) {
            int t = 8 * tb + m;
            if (s >= t) ov[m] = 0.f;
        }
        *(float4*)&Gp[s * 64 + 8 * tb]     = make_float4(ov[0], ov[1], ov[2], ov[3]);
        *(float4*)&Gp[s * 64 + 8 * tb + 4] = make_float4(ov[4], ov[5], ov[6], ov[7]);
    }
}

// ---------------- Kernel 3: chunked delta-memory scan ----------------
struct ScanSmem {
    float Ksh[2][64][68];
    float Gsh[2][64][64];
    float Mt[64][20];
    float Dsh[64][16];
    float Ush[64][16];
    float nbsh[2][64];
};
#define SCAN_SMEM_BYTES sizeof(ScanSmem)

__global__ void __launch_bounds__(128, 1) scan2_kernel(const int* __restrict__ seq)
{
    extern __shared__ __align__(16) char smem_raw[];
    ScanSmem* S = (ScanSmem*)smem_raw;

    const int b = blockIdx.x;
    const int i0 = blockIdx.y * 16;
    const int z = threadIdx.x;
    const int r = z >> 1, ih = z & 1;
    const int il = z >> 3, tq = z & 7;
    const int lane = z & 31;
    const int srcbase = lane & 24;
    const int* seqb = seq + (size_t)b * Ldim;

    for (int idx = z; idx < 64 * 20; idx += 128) ((float*)S->Mt)[idx] = 0.f;

    int tokA = 0, tokB = 0; bool vA = false, vB = false;
    {
        int g0 = r;
        vA = g0 < NSTEP; tokA = vA ? seqb[g0] : 0;
        int g1 = 64 + r;
        vB = g1 < NSTEP; tokB = vB ? seqb[g1] : 0;
    }

    { // fill buffer 0
        if (vA) {
            const float* src = g_htab + (size_t)tokA * Hdim + ih * 32;
            unsigned dst = (unsigned)__cvta_generic_to_shared(&S->Ksh[0][r][ih * 32]);
            #pragma unroll
            for (int m = 0; m < 8; m++) cpasync16(dst + m * 16, src + m * 4);
            if (ih == 0)
                cpasync4((unsigned)__cvta_generic_to_shared(&S->nbsh[0][r]), g_nbeta + tokA);
        } else {
            float4 zz = make_float4(0.f, 0.f, 0.f, 0.f);
            #pragma unroll
            for (int m = 0; m < 8; m++) *(float4*)&S->Ksh[0][r][ih * 32 + 4 * m] = zz;
            if (ih == 0) S->nbsh[0][r] = 0.f;
        }
        const float* gsrc = g_G + ((size_t)b * CNKS << 12);
        unsigned gdst = (unsigned)__cvta_generic_to_shared(&S->Gsh[0][0][0]);
        #pragma unroll
        for (int m = 0; m < 8; m++) {
            int idx = z + 128 * m;
            cpasync16(gdst + idx * 16, gsrc + idx * 4);
        }
        asm volatile("cp.async.commit_group;" ::: "memory");
        asm volatile("cp.async.wait_group 0;" ::: "memory");
        __syncthreads();
    }

    #pragma unroll 1
    for (int c = 0; c < CNKS; ++c) {
        const int cur = c & 1;

        if (c + 1 < CNKS) {
            const int nb_ = cur ^ 1;
            if (vB) {
                const float* src = g_htab + (size_t)tokB * Hdim + ih * 32;
                unsigned dst = (unsigned)__cvta_generic_to_shared(&S->Ksh[nb_][r][ih * 32]);
                #pragma unroll
                for (int m = 0; m < 8; m++) cpasync16(dst + m * 16, src + m * 4);
                if (ih == 0)
                    cpasync4((unsigned)__cvta_generic_to_shared(&S->nbsh[nb_][r]), g_nbeta + tokB);
            } else {
                float4 zz = make_float4(0.f, 0.f, 0.f, 0.f);
                #pragma unroll
                for (int m = 0; m < 8; m++) *(float4*)&S->Ksh[nb_][r][ih * 32 + 4 * m] = zz;
                if (ih == 0) S->nbsh[nb_][r] = 0.f;
            }
            const float* gsrc = g_G + (((size_t)b * CNKS + (c + 1)) << 12);
            unsigned gdst = (unsigned)__cvta_generic_to_shared(&S->Gsh[nb_][0][0]);
            #pragma unroll
            for (int m = 0; m < 8; m++) {
                int idx = z + 128 * m;
                cpasync16(gdst + idx * 16, gsrc + idx * 4);
            }
        }
        asm volatile("cp.async.commit_group;" ::: "memory");

        {
            int c2 = c + 2;
            int g2 = c2 * 64 + r;
            vB = (c2 < CNKS) && (g2 < NSTEP);
            tokB = vB ? seqb[vB ? g2 : 0] : 0;
        }

        // ---- phase 1 (packed): D[t][i] = sum_j M[i][j]*K[t][j] ----
        {
            const int t = r;
            u64 a[4] = {0ULL, 0ULL, 0ULL, 0ULL};
            const float* Kr = &S->Ksh[cur][t][0];
            #pragma unroll 4
            for (int j = 0; j < 64; j++) {
                float kv = Kr[j];
                u64 kb = pk2(kv, kv);
                const u64* mp = (const u64*)&S->Mt[j][8 * ih];
                a[0] = ff2(kb, mp[0], a[0]);
                a[1] = ff2(kb, mp[1], a[1]);
                a[2] = ff2(kb, mp[2], a[2]);
                a[3] = ff2(kb, mp[3], a[3]);
            }
            u64* dp = (u64*)&S->Dsh[t][8 * ih];
            dp[0] = a[0]; dp[1] = a[1]; dp[2] = a[2]; dp[3] = a[3];
        }
        __syncthreads();

        // ---- phase 2: owner-blocked triangular solve ----
        {
            const int gi = i0 + il;
            const float* Ks = &S->Ksh[cur][0][0];
            const float* nbp = &S->nbsh[cur][0];
            const float* Gp = &S->Gsh[cur][0][0];

            u64 vpk[4];
            #pragma unroll
            for (int m = 0; m < 4; m++)
                vpk[m] = pk2(S->Dsh[8 * tq + 2 * m][il], S->Dsh[8 * tq + 2 * m + 1][il]);

            #pragma unroll 1
            for (int blk = 0; blk < 8; ++blk) {
                const int s0 = blk * 8;
                float ub[8];
                if (tq == blk) {
                    float sv[8];
                    up2(vpk[0], sv[0], sv[1]); up2(vpk[1], sv[2], sv[3]);
                    up2(vpk[2], sv[4], sv[5]); up2(vpk[3], sv[6], sv[7]);
                    float kc[8], nbl[8];
                    #pragma unroll
                    for (int rr = 0; rr < 8; rr++) {
                        kc[rr]  = Ks[(s0 + rr) * 68 + gi];
                        nbl[rr] = nbp[s0 + rr];
                    }
                    // in-block G rows, depth-2 prefetch
                    const float* Grow = Gp + s0 * 64 + s0;
                    u64 g0[4], g1[4], g2[4];
                    #pragma unroll
                    for (int m = 0; m < 4; m++) {
                        g0[m] = *(const u64*)(Grow + 2 * m);
                        g1[m] = *(const u64*)(Grow + 64 + 2 * m);
                    }
                    #pragma unroll
                    for (int rr = 0; rr < 8; rr++) {
                        if (rr < 6) {
                            const float* gp2 = Grow + (rr + 2) * 64;
                            #pragma unroll
                            for (int m = 0; m < 4; m++) g2[m] = *(const u64*)(gp2 + 2 * m);
                        }
                        float cu = fmaf(nbl[rr], sv[rr], kc[rr]);
                        ub[rr] = cu;
                        float gw[8];
                        up2(g0[0], gw[0], gw[1]); up2(g0[1], gw[2], gw[3]);
                        up2(g0[2], gw[4], gw[5]); up2(g0[3], gw[6], gw[7]);
                        #pragma unroll
                        for (int m = 0; m < 8; m++)
                            if (m > rr) sv[m] = fmaf(cu, gw[m], sv[m]);
                        #pragma unroll
                        for (int m = 0; m < 4; m++) { g0[m] = g1[m]; g1[m] = g2[m]; }
                    }
                } else {
                    #pragma unroll
                    for (int rr = 0; rr < 8; rr++) ub[rr] = 0.f;
                }
                // broadcast u values for this block
                #pragma unroll
                for (int rr = 0; rr < 8; rr++)
                    ub[rr] = __shfl_sync(0xffffffffu, ub[rr], srcbase | blk);
                if (tq == 0) {
                    #pragma unroll
                    for (int rr = 0; rr < 8; rr++) S->Ush[s0 + rr][il] = ub[rr];
                }
                // packed rank-8 update for future t-groups
                if (tq > blk) {
                    #pragma unroll
                    for (int rr = 0; rr < 8; rr++) {
                        u64 ubb = pk2(ub[rr], ub[rr]);
                        const u64* gp = (const u64*)&Gp[(s0 + rr) * 64 + 8 * tq];
                        vpk[0] = ff2(ubb, gp[0], vpk[0]);
                        vpk[1] = ff2(ubb, gp[1], vpk[1]);
                        vpk[2] = ff2(ubb, gp[2], vpk[2]);
                        vpk[3] = ff2(ubb, gp[3], vpk[3]);
                    }
                }
            }
        }
        __syncthreads();

        // ---- phase 3 (packed): M[i][j] += sum_s u[s][i]*K[s][j] ----
        {
            const int j = r;
            u64* mp = (u64*)&S->Mt[j][8 * ih];
            u64 m0 = mp[0], m1 = mp[1], m2 = mp[2], m3 = mp[3];
            const float* Ks = &S->Ksh[cur][0][0];
            #pragma unroll 4
            for (int s = 0; s < 64; s++) {
                float kv = Ks[s * 68 + j];
                u64 kb = pk2(kv, kv);
                const u64* up = (const u64*)&S->Ush[s][8 * ih];
                m0 = ff2(kb, up[0], m0);
                m1 = ff2(kb, up[1], m1);
                m2 = ff2(kb, up[2], m2);
                m3 = ff2(kb, up[3], m3);
            }
            mp[0] = m0; mp[1] = m1; mp[2] = m2; mp[3] = m3;
        }
        asm volatile("cp.async.wait_group 0;" ::: "memory");
        __syncthreads();
    }

    for (int idx = z; idx < 16 * 64; idx += 128) {
        int ii = idx & 15, j = idx >> 4;
        g_M[((size_t)b * Hdim + i0 + ii) * Hdim + j] = S->Mt[j][ii];
    }
}

// ---------------- Kernel 4: readout ----------------
__global__ void __launch_bounds__(64) readout_kernel(
    const int* __restrict__ seq, const int* __restrict__ read_pos,
    const float* __restrict__ rp_w, const float* __restrict__ rp_b)
{
    __shared__ float qs[Hdim];
    __shared__ float rs[Hdim];
    const int b = blockIdx.x;
    const int tid = threadIdx.x;

    int rp = read_pos[0];
    if (rp < 0) rp += Ldim;
    int tok = seq[(size_t)b * Ldim + rp];
    qs[tid] = g_htab[(size_t)tok * Hdim + tid];
    __syncthreads();

    const float* Mi = g_M + ((size_t)b * Hdim + tid) * Hdim;
    float r = 0.f;
    #pragma unroll 8
    for (int j = 0; j < Hdim; j++) r = fmaf(Mi[j], qs[j], r);
    rs[tid] = r;
    __syncthreads();

    float acc = rp_b[tid];
    #pragma unroll 8
    for (int k = 0; k < Hdim; k++) acc = fmaf(rs[k], rp_w[k * Hdim + tid], acc);
    g_rr[b * Hdim + tid] = acc;
}

// ---------------- Kernel 5: logits ----------------
__global__ void __launch_bounds__(128) logits_kernel(
    const float* __restrict__ out_w, const float* __restrict__ out_b,
    float* __restrict__ out)
{
    __shared__ float rrs[8 * Hdim];
    const int tid = threadIdx.x;
    const int bg = blockIdx.y;
    for (int idx = tid; idx < 8 * Hdim; idx += 128)
        rrs[idx] = g_rr[bg * 8 * Hdim + idx];
    __syncthreads();

    const int v = blockIdx.x * 128 + tid;
    if (v >= Vdim) return;

    float acc[8];
    #pragma unroll
    for (int bb = 0; bb < 8; bb++) acc[bb] = 0.f;
    #pragma unroll 8
    for (int i = 0; i < Hdim; i++) {
        float wv = out_w[(size_t)i * Vdim + v];
        #pragma unroll
        for (int bb = 0; bb < 8; bb++)
            acc[bb] = fmaf(rrs[bb * Hdim + i], wv, acc[bb]);
    }
    float ob = out_b[v];
    #pragma unroll
    for (int bb = 0; bb < 8; bb++)
        out[(size_t)(bg * 8 + bb) * Vdim + v] = acc[bb] + ob;
}

// ----------------------------------------------------------------
extern "C" void kernel_launch(void* const* d_in, const int* in_sizes, int n_in,
                              void* d_out, int out_size)
{
    const int*   seq      = (const int*)d_in[0];
    const int*   read_pos = (const int*)d_in[1];
    const float* embed    = (const float*)d_in[2];
    const float* w1       = (const float*)d_in[3];
    const float* b1       = (const float*)d_in[4];
    const float* w2       = (const float*)d_in[5];
    const float* b2       = (const float*)d_in[6];
    const float* ln_g     = (const float*)d_in[7];
    const float* ln_b     = (const float*)d_in[8];
    const float* rp_w     = (const float*)d_in[9];
    const float* rp_b     = (const float*)d_in[10];
    const float* out_w    = (const float*)d_in[11];
    const float* out_b    = (const float*)d_in[12];
    float* out = (float*)d_out;

    static bool attr_done = false;
    if (!attr_done) {
        cudaFuncSetAttribute(scan2_kernel,
                             cudaFuncAttributeMaxDynamicSharedMemorySize,
                             (int)SCAN_SMEM_BYTES);
        cudaFuncSetAttribute(build_table_kernel,
                             cudaFuncAttributeMaxDynamicSharedMemorySize,
                             (int)TAB_SMEM_BYTES);
        attr_done = true;
    }

    build_table_kernel<<<(Vdim + 15) / 16, 128, TAB_SMEM_BYTES>>>(embed, w1, b1, w2, b2, ln_g, ln_b);
    gram_kernel<<<dim3(Bdim, CNKS), 128>>>(seq);
    scan2_kernel<<<dim3(Bdim, 4), 128, SCAN_SMEM_BYTES>>>(seq);
    readout_kernel<<<Bdim, Hdim>>>(seq, read_pos, rp_w, rp_b);
    logits_kernel<<<dim3((Vdim + 127) / 128, 4), 128>>>(out_w, out_b, out);
}